// round 2
// baseline (speedup 1.0000x reference)
#include <cuda_runtime.h>
#include <cstdint>
#include <cstddef>

#define TOKENS 8192
#define DIN    4096
#define DOUT   16384

// ---------------- device scratch (static: no runtime allocation) ----------------
static __device__ int8_t g_A1[(size_t)TOKENS * DIN];   // 32 MB  digit-1 of x
static __device__ int8_t g_A2[(size_t)TOKENS * DIN];   // 32 MB  digit-2 (residual) of x
static __device__ int8_t g_W8[(size_t)DOUT   * DIN];   // 64 MB  int8 weights (exact)
static __device__ float  g_s1[TOKENS];                 // per-token scale

// ---------------- helpers ----------------
__device__ __forceinline__ void cp16(void* dst_smem, const void* src) {
    uint32_t d;
    asm("{ .reg .u64 t; cvta.to.shared.u64 t, %1; cvt.u32.u64 %0, t; }" : "=r"(d) : "l"(dst_smem));
    asm volatile("cp.async.cg.shared.global [%0], [%1], 16;" :: "r"(d), "l"(src));
}
__device__ __forceinline__ void imma16832(int* d, const uint32_t* a, const uint32_t* b) {
    asm volatile(
        "mma.sync.aligned.m16n8k32.row.col.s32.s8.s8.s32 "
        "{%0,%1,%2,%3}, {%4,%5,%6,%7}, {%8,%9}, {%0,%1,%2,%3};"
        : "+r"(d[0]), "+r"(d[1]), "+r"(d[2]), "+r"(d[3])
        : "r"(a[0]), "r"(a[1]), "r"(a[2]), "r"(a[3]), "r"(b[0]), "r"(b[1]));
}

// ---------------- convert kernels ----------------
__global__ void __launch_bounds__(256) convert_w_kernel(const int* __restrict__ q) {
    size_t i = (size_t)blockIdx.x * 256 + threadIdx.x;   // one int4 -> char4
    int4 v = ((const int4*)q)[i];
    char4 o;
    o.x = (char)v.x; o.y = (char)v.y; o.z = (char)v.z; o.w = (char)v.w;
    ((char4*)g_W8)[i] = o;
}

__global__ void __launch_bounds__(256) quant_x_kernel(const float* __restrict__ x) {
    const int t = blockIdx.x;                            // one token per CTA
    const float4* row = (const float4*)(x + (size_t)t * DIN);
    float4 v[4];
    float m = 0.f;
#pragma unroll
    for (int j = 0; j < 4; ++j) {
        v[j] = row[threadIdx.x + j * 256];
        m = fmaxf(m, fmaxf(fmaxf(fabsf(v[j].x), fabsf(v[j].y)),
                           fmaxf(fabsf(v[j].z), fabsf(v[j].w))));
    }
#pragma unroll
    for (int o = 16; o > 0; o >>= 1) m = fmaxf(m, __shfl_xor_sync(0xFFFFFFFFu, m, o));
    __shared__ float wmax[8];
    if ((threadIdx.x & 31) == 0) wmax[threadIdx.x >> 5] = m;
    __syncthreads();
    float amax = wmax[0];
#pragma unroll
    for (int w = 1; w < 8; ++w) amax = fmaxf(amax, wmax[w]);
    amax = fmaxf(amax, 1e-30f);

    const float s1   = amax * (1.f / 127.f);
    const float inv1 = 127.f / amax;
    const float s2   = s1 * (1.f / 254.f);
    const float inv2 = 254.f / s1;
    if (threadIdx.x == 0) g_s1[t] = s1;

    char4* o1 = (char4*)(g_A1 + (size_t)t * DIN);
    char4* o2 = (char4*)(g_A2 + (size_t)t * DIN);
#pragma unroll
    for (int j = 0; j < 4; ++j) {
        float f[4] = {v[j].x, v[j].y, v[j].z, v[j].w};
        char  c1[4], c2[4];
#pragma unroll
        for (int e = 0; e < 4; ++e) {
            float q1 = rintf(f[e] * inv1);
            float r  = fmaf(-q1, s1, f[e]);
            float q2 = rintf(r * inv2);
            q2 = fminf(fmaxf(q2, -127.f), 127.f);
            c1[e] = (char)(int)q1;
            c2[e] = (char)(int)q2;
        }
        o1[threadIdx.x + j * 256] = make_char4(c1[0], c1[1], c1[2], c1[3]);
        o2[threadIdx.x + j * 256] = make_char4(c2[0], c2[1], c2[2], c2[3]);
    }
}

// ---------------- GEMM ----------------
// CTA tile 256(M: 128 tokens x 2 digits) x 128(N), K-tile 64.
// 512 threads = 16 warps (4x4), warp tile 64x32, m16n8k32 s8 IMMA, 5-stage cp.async.
static constexpr int PITCH       = 80;                    // 64B row + 16B pad (conflict-free)
static constexpr int A_BYTES     = 256 * PITCH;           // 20480
static constexpr int STAGE_BYTES = A_BYTES + 128 * PITCH; // 30720
static constexpr int STAGES      = 5;
static constexpr int S1_OFF      = STAGES * STAGE_BYTES;  // 153600
static constexpr int SMEM_BYTES  = S1_OFF + 512;          // 154112
static constexpr int EPI_PITCH   = 132;                   // floats

__device__ __forceinline__ void load_stage(char* smem, int stg, int m0, int n0, int k0) {
    char* base = smem + stg * STAGE_BYTES;
    const int tid = threadIdx.x;
#pragma unroll
    for (int t = 0; t < 3; ++t) {
        int c = tid + t * 512;            // 1536 x 16B chunks
        if (c < 1024) {                   // A: 256 rows x 64B
            int row = c >> 2, ch = c & 3;
            const int8_t* src = (row < 128 ? g_A1 + (size_t)(m0 + row) * DIN
                                           : g_A2 + (size_t)(m0 + row - 128) * DIN)
                                + k0 + ch * 16;
            cp16(base + row * PITCH + ch * 16, src);
        } else {                          // B: 128 rows x 64B
            int l = c - 1024, row = l >> 2, ch = l & 3;
            const int8_t* src = g_W8 + (size_t)(n0 + row) * DIN + k0 + ch * 16;
            cp16(base + A_BYTES + row * PITCH + ch * 16, src);
        }
    }
}

__global__ void __launch_bounds__(512, 1)
qlinear_gemm(const int* __restrict__ q_bias, const float* __restrict__ scale,
             const float* __restrict__ bias_scale, float* __restrict__ out)
{
    extern __shared__ char smem[];
    const int tid  = threadIdx.x;
    const int wid  = tid >> 5;
    const int lane = tid & 31;
    const int wrow = wid >> 2;            // 0..3 : rows 64*wrow..+63
    const int wcol = wid & 3;             // 0..3 : cols 32*wcol..+31
    const int r    = lane >> 2;           // 0..7
    const int kg   = lane & 3;            // 0..3

    // grouped rasterization: 8 M-tiles per group so A + W slices stay in L2
    const int bid   = blockIdx.x;
    const int group = bid >> 10;          // 8 m-tiles * 128 n-tiles
    const int m0    = ((group << 3) + (bid & 7)) * 128;     // token base
    const int n0    = ((bid >> 3) & 127) * 128;

    float* s1_sm = (float*)(smem + S1_OFF);
    if (tid < 128) s1_sm[tid] = g_s1[m0 + tid];

    // prologue: 3 stages
    load_stage(smem, 0, m0, n0, 0);
    asm volatile("cp.async.commit_group;" ::: "memory");
    load_stage(smem, 1, m0, n0, 64);
    asm volatile("cp.async.commit_group;" ::: "memory");
    load_stage(smem, 2, m0, n0, 128);
    asm volatile("cp.async.commit_group;" ::: "memory");

    int acc[4][4][4] = {};

#pragma unroll 1
    for (int i = 0; i < 64; ++i) {
        if (i + 3 < 64) load_stage(smem, (i + 3) % STAGES, m0, n0, (i + 3) * 64);
        asm volatile("cp.async.commit_group;" ::: "memory");
        asm volatile("cp.async.wait_group 3;" ::: "memory");
        __syncthreads();

        const char* sA = smem + (i % STAGES) * STAGE_BYTES;
        const char* sB = sA + A_BYTES;
        const int aBase = (wrow * 64 + r) * PITCH + kg * 4;
        const int bBase = (wcol * 32 + r) * PITCH + kg * 4;
#pragma unroll
        for (int ks = 0; ks < 2; ++ks) {
            uint32_t a[4][4], b[4][2];
#pragma unroll
            for (int mt = 0; mt < 4; ++mt) {
                int o = aBase + mt * 16 * PITCH + ks * 32;
                a[mt][0] = *(const uint32_t*)(sA + o);
                a[mt][1] = *(const uint32_t*)(sA + o + 8 * PITCH);
                a[mt][2] = *(const uint32_t*)(sA + o + 16);
                a[mt][3] = *(const uint32_t*)(sA + o + 8 * PITCH + 16);
            }
#pragma unroll
            for (int nt = 0; nt < 4; ++nt) {
                int o = bBase + nt * 8 * PITCH + ks * 32;
                b[nt][0] = *(const uint32_t*)(sB + o);
                b[nt][1] = *(const uint32_t*)(sB + o + 16);
            }
#pragma unroll
            for (int mt = 0; mt < 4; ++mt)
#pragma unroll
                for (int nt = 0; nt < 4; ++nt)
                    imma16832(acc[mt][nt], a[mt], b[nt]);
        }
    }
    __syncthreads();

    // ---------------- epilogue ----------------
    const float sc  = scale[0];
    const float bsc = bias_scale[0];
    float* stage = (float*)smem;          // 128 x 132 floats (reuses pipeline smem)

    if (wrow >= 2) {                      // digit-2: write s2*acc to SMEM
#pragma unroll
        for (int mt = 0; mt < 4; ++mt) {
            const int t0 = (wrow - 2) * 64 + mt * 16 + r;
            const float s2a = s1_sm[t0]     * (1.f / 254.f);
            const float s2b = s1_sm[t0 + 8] * (1.f / 254.f);
#pragma unroll
            for (int nt = 0; nt < 4; ++nt) {
                const int col = wcol * 32 + nt * 8 + kg * 2;
                float2 p0 = make_float2(acc[mt][nt][0] * s2a, acc[mt][nt][1] * s2a);
                float2 p1 = make_float2(acc[mt][nt][2] * s2b, acc[mt][nt][3] * s2b);
                *(float2*)(stage + (size_t)t0 * EPI_PITCH + col)       = p0;
                *(float2*)(stage + (size_t)(t0 + 8) * EPI_PITCH + col) = p1;
            }
        }
    }
    __syncthreads();

    if (wrow < 2) {                       // digit-1: combine + bias + store
#pragma unroll
        for (int nt = 0; nt < 4; ++nt) {
            const int col = wcol * 32 + nt * 8 + kg * 2;
            const int2 qb = *(const int2*)(q_bias + n0 + col);
            const float b0 = qb.x * bsc, b1 = qb.y * bsc;
#pragma unroll
            for (int mt = 0; mt < 4; ++mt) {
                const int t0 = wrow * 64 + mt * 16 + r;
                const float s1a = s1_sm[t0], s1b = s1_sm[t0 + 8];
                const float* st0 = stage + (size_t)t0 * EPI_PITCH + col;
                const float* st1 = stage + (size_t)(t0 + 8) * EPI_PITCH + col;
                float2 r0, r1;
                r0.x = sc * fmaf(acc[mt][nt][0], s1a, st0[0]) + b0;
                r0.y = sc * fmaf(acc[mt][nt][1], s1a, st0[1]) + b1;
                r1.x = sc * fmaf(acc[mt][nt][2], s1b, st1[0]) + b0;
                r1.y = sc * fmaf(acc[mt][nt][3], s1b, st1[1]) + b1;
                *(float2*)(out + (size_t)(m0 + t0) * DOUT + n0 + col)     = r0;
                *(float2*)(out + (size_t)(m0 + t0 + 8) * DOUT + n0 + col) = r1;
            }
        }
    }
}

// ---------------- launch ----------------
extern "C" void kernel_launch(void* const* d_in, const int* in_sizes, int n_in,
                              void* d_out, int out_size) {
    const float* x   = (const float*)d_in[0];
    const int*   qw  = (const int*)d_in[1];
    const int*   qb  = (const int*)d_in[2];
    const float* sc  = (const float*)d_in[3];
    const float* bsc = (const float*)d_in[4];
    float* out = (float*)d_out;

    cudaFuncSetAttribute(qlinear_gemm, cudaFuncAttributeMaxDynamicSharedMemorySize, SMEM_BYTES);

    convert_w_kernel<<<(DOUT * (size_t)DIN) / 4 / 256, 256>>>(qw);   // 65536 blocks
    quant_x_kernel<<<TOKENS, 256>>>(x);                              // 8192 blocks
    qlinear_gemm<<<(TOKENS / 128) * (DOUT / 128), 512, SMEM_BYTES>>>(qb, sc, bsc, out);
}